// round 14
// baseline (speedup 1.0000x reference)
#include <cuda_runtime.h>
#include <cuda_fp16.h>
#include <cstdint>
#include <cstddef>

// Problem sizes
static constexpr int M = 8192;   // tokens
static constexpr int K = 4096;   // in features
static constexpr int N = 4096;   // out features

// GEMM tiling: CTA 128x128x64, 8 warps (4 M x 2 N), warp tile 32x64, 256 threads.
// 3 stages x 32KB = 97KB -> 2 CTAs/SM: co-resident CTA hides barrier skew.
static constexpr int BM = 128;
static constexpr int BN = 128;
static constexpr int BK = 64;                    // 64 fp16 = 128 B per row
static constexpr int NIT = K / BK;               // 64
static constexpr int STAGES = 3;
static constexpr int A_STAGE_BYTES = BM * 128;   // 16 KB
static constexpr int B_STAGE_BYTES = BN * 128;   // 16 KB
static constexpr int STAGE_BYTES = A_STAGE_BYTES + B_STAGE_BYTES;  // 32 KB
static constexpr int DYN_SMEM = 1024 + STAGES * STAGE_BYTES;       // ~97 KB

// Scratch (static device arrays are allowed; cudaMalloc is not)
__device__ __half g_A[(size_t)M * K];   // sign(x) as fp16, [M,K] row-major
__device__ __half g_B[(size_t)N * K];   // W^T as fp16,     [N,K] row-major

// ---------------- PTX helpers (baseline sm_103, no 'a' features) ----------------
__device__ __forceinline__ uint32_t smem_u32(const void* p) {
    uint32_t a;
    asm("{ .reg .u64 t; cvta.to.shared.u64 t, %1; cvt.u32.u64 %0, t; }" : "=r"(a) : "l"(p));
    return a;
}
__device__ __forceinline__ void cp_async16(uint32_t s, const void* g) {
    asm volatile("cp.async.cg.shared.global [%0], [%1], 16;" :: "r"(s), "l"(g));
}
__device__ __forceinline__ void cp_commit() {
    asm volatile("cp.async.commit_group;" ::: "memory");
}
template <int NWAIT>
__device__ __forceinline__ void cp_wait() {
    asm volatile("cp.async.wait_group %0;" :: "n"(NWAIT) : "memory");
}
__device__ __forceinline__ void ldsm_x4(uint32_t& r0, uint32_t& r1, uint32_t& r2, uint32_t& r3,
                                        uint32_t addr) {
    asm volatile("ldmatrix.sync.aligned.m8n8.x4.shared.b16 {%0,%1,%2,%3}, [%4];"
                 : "=r"(r0), "=r"(r1), "=r"(r2), "=r"(r3) : "r"(addr));
}
__device__ __forceinline__ void mma16816(float& d0, float& d1, float& d2, float& d3,
                                         uint32_t a0, uint32_t a1, uint32_t a2, uint32_t a3,
                                         uint32_t b0, uint32_t b1) {
    asm volatile(
        "mma.sync.aligned.m16n8k16.row.col.f32.f16.f16.f32 "
        "{%0,%1,%2,%3}, {%4,%5,%6,%7}, {%8,%9}, {%0,%1,%2,%3};"
        : "+f"(d0), "+f"(d1), "+f"(d2), "+f"(d3)
        : "r"(a0), "r"(a1), "r"(a2), "r"(a3), "r"(b0), "r"(b1));
}
// SW128-style swizzle: XOR 16B-chunk index with (row & 7)
__device__ __forceinline__ uint32_t swz(uint32_t off) { return off ^ ((off >> 3) & 0x70); }

// ---------------- Kernel 1: fused prep ----------------
static constexpr int BIN_BLOCKS = 4096;
static constexpr int WCONV_BLOCKS = (N / 32) * (K / 64);   // 8192
__global__ void prep_kernel(const float4* __restrict__ x4, const float* __restrict__ W) {
    if (blockIdx.x < BIN_BLOCKS) {
        const int n4 = (M * K) / 4;
        int i = blockIdx.x * 256 + threadIdx.x;
        const int stride = BIN_BLOCKS * 256;
        const __half one = __float2half_rn(1.0f);
        const __half neg = __float2half_rn(-1.0f);
        uint2* a8 = reinterpret_cast<uint2*>(g_A);
        for (; i < n4; i += stride) {
            float4 v = x4[i];
            __half2 h0 = __halves2half2(v.x > 0.0f ? one : neg, v.y > 0.0f ? one : neg);
            __half2 h1 = __halves2half2(v.z > 0.0f ? one : neg, v.w > 0.0f ? one : neg);
            uint2 pk;
            pk.x = *reinterpret_cast<uint32_t*>(&h0);
            pk.y = *reinterpret_cast<uint32_t*>(&h1);
            a8[i] = pk;
        }
    } else {
        __shared__ float t[64][33];
        const int bid = blockIdx.x - BIN_BLOCKS;
        const int n0 = (bid & 127) * 32;       // N/32 = 128
        const int k0 = (bid >> 7) * 64;
        const int tx = threadIdx.x & 31, ty = threadIdx.x >> 5;   // 32 x 8
#pragma unroll
        for (int r = 0; r < 8; ++r)
            t[ty + 8 * r][tx] = W[(size_t)(k0 + ty + 8 * r) * N + n0 + tx];
        __syncthreads();
#pragma unroll
        for (int r = 0; r < 4; ++r) {
            const int n = ty + 8 * r;          // 0..31
            const __half2 h = __floats2half2_rn(t[2 * tx][n], t[2 * tx + 1][n]);
            *reinterpret_cast<__half2*>(g_B + (size_t)(n0 + n) * K + k0 + 2 * tx) = h;
        }
    }
}

// ---------------- Kernel 2: mma.sync fp16 GEMM + bias ----------------
__device__ __forceinline__ void load_stage(uint32_t tile0, int m0, int n0, int k_it, int slot,
                                           int tid) {
    const int k0 = k_it * BK;
    const uint32_t sa = tile0 + slot * STAGE_BYTES;
    const uint32_t sbm = sa + A_STAGE_BYTES;
    // A: 128 rows x 8 chunks = 1024; B: 128 rows x 8 chunks = 1024; 2048 / 256 thr = 8 each
#pragma unroll
    for (int c = tid; c < 2048; c += 256) {
        const int r = (c & 1023) >> 3, j = c & 7;
        const uint32_t so = swz((uint32_t)(r * 128 + j * 16));
        if (c < 1024)
            cp_async16(sa + so, g_A + (((size_t)(m0 + r)) << 12) + k0 + (j << 3));
        else
            cp_async16(sbm + so, g_B + (((size_t)(n0 + r)) << 12) + k0 + (j << 3));
    }
}

// Load one kk-step's fragments for this warp: A 2x ldsm.x4, B 4x ldsm.x4.
__device__ __forceinline__ void load_frags(uint32_t af[2][4], uint32_t bf[8][2],
                                           uint32_t sa, uint32_t sbm,
                                           const uint32_t aoff[2], const uint32_t boff[4],
                                           uint32_t kx) {
#pragma unroll
    for (int mi = 0; mi < 2; ++mi)
        ldsm_x4(af[mi][0], af[mi][1], af[mi][2], af[mi][3], sa + (aoff[mi] ^ kx));
#pragma unroll
    for (int pj = 0; pj < 4; ++pj) {
        uint32_t r0, r1, r2, r3;
        ldsm_x4(r0, r1, r2, r3, sbm + (boff[pj] ^ kx));
        bf[pj * 2 + 0][0] = r0; bf[pj * 2 + 0][1] = r1;
        bf[pj * 2 + 1][0] = r2; bf[pj * 2 + 1][1] = r3;
    }
}

__global__ void __launch_bounds__(256, 2) gemm_kernel(float* __restrict__ out,
                                                      const float* __restrict__ bias) {
    extern __shared__ char smem[];
    const uint32_t tile0 = (smem_u32(smem) + 1023) & ~1023u;
    const int tid = threadIdx.x;
    const int wid = tid >> 5;
    const int lane = tid & 31;
    const int m0 = blockIdx.y * BM;
    const int n0 = blockIdx.x * BN;
    const int warp_m = wid & 3;        // 0..3 -> 32 rows each
    const int warp_n = wid >> 2;       // 0..1 -> 64 cols each

    // Swizzled ldmatrix offsets (kk=0).
    uint32_t aoff[2];
#pragma unroll
    for (int mi = 0; mi < 2; ++mi) {
        const int row = warp_m * 32 + mi * 16 + (lane & 15);
        aoff[mi] = swz((uint32_t)(row * 128) + (uint32_t)((lane >> 4) << 4));
    }
    uint32_t boff[4];
#pragma unroll
    for (int pj = 0; pj < 4; ++pj) {
        const int row = warp_n * 64 + pj * 16 + (lane & 7) + ((lane >> 4) << 3);
        boff[pj] = swz((uint32_t)(row * 128) + (uint32_t)(((lane >> 3) & 1) << 4));
    }

    float acc[2][8][4];   // [mi][nj][c]  (64 regs)
#pragma unroll
    for (int mi = 0; mi < 2; ++mi)
#pragma unroll
        for (int nj = 0; nj < 8; ++nj)
#pragma unroll
            for (int c = 0; c < 4; ++c) acc[mi][nj][c] = 0.0f;

    // Prologue: fill stages 0,1; both must be resident before the loop.
#pragma unroll
    for (int p = 0; p < STAGES - 1; ++p) {
        load_stage(tile0, m0, n0, p, p, tid);
        cp_commit();
    }
    cp_wait<0>();
    __syncthreads();

    // Full kk-step double buffer: A 2x8 regs, B 2x16 regs.
    uint32_t af[2][2][4];
    uint32_t bf[2][8][2];
    load_frags(af[0], bf[0], tile0, tile0 + A_STAGE_BYTES, aoff, boff, 0);

    for (int it = 0; it < NIT; ++it) {
        const uint32_t sa = tile0 + (it % STAGES) * STAGE_BYTES;
        const uint32_t sbm = sa + A_STAGE_BYTES;
        const uint32_t sa_n = tile0 + ((it + 1) % STAGES) * STAGE_BYTES;
        const uint32_t sbm_n = sa_n + A_STAGE_BYTES;
        const bool has_next = (it + 1 < NIT);

        // Issue loads for stage it+2 into slot (it+2)%3 (freed by barrier at end of it-1).
        if (it + STAGES - 1 < NIT)
            load_stage(tile0, m0, n0, it + STAGES - 1, (it + STAGES - 1) % STAGES, tid);
        cp_commit();

#pragma unroll
        for (int kk = 0; kk < 4; ++kk) {
            const int cur = kk & 1, nxt = cur ^ 1;
            // Prefetch kk+1 (same stage) or next iter's kk0 (stage it+1, resident since
            // wait<0> at end of iter it-1 / prologue).
            if (kk < 3)
                load_frags(af[nxt], bf[nxt], sa, sbm, aoff, boff, (uint32_t)((kk + 1) << 5));
            else if (has_next)
                load_frags(af[nxt], bf[nxt], sa_n, sbm_n, aoff, boff, 0);
            // 16 MMAs of latency cover for the prefetch above.
#pragma unroll
            for (int mi = 0; mi < 2; ++mi)
#pragma unroll
                for (int nj = 0; nj < 8; ++nj)
                    mma16816(acc[mi][nj][0], acc[mi][nj][1], acc[mi][nj][2], acc[mi][nj][3],
                             af[cur][mi][0], af[cur][mi][1], af[cur][mi][2], af[cur][mi][3],
                             bf[cur][nj][0], bf[cur][nj][1]);
        }

        // End-of-iter: all issued loads complete (stage it+2 resident for next iter's
        // kk3 prefetch); barrier frees slot it%3 for next iter's writers.
        cp_wait<0>();
        __syncthreads();
    }

    // Epilogue
    const int g = lane >> 2, tg = lane & 3;
    float bcol0[8], bcol1[8];
#pragma unroll
    for (int nj = 0; nj < 8; ++nj) {
        const int col = n0 + warp_n * 64 + nj * 8 + tg * 2;
        bcol0[nj] = __ldg(bias + col);
        bcol1[nj] = __ldg(bias + col + 1);
    }
#pragma unroll
    for (int mi = 0; mi < 2; ++mi) {
        const int r0 = m0 + warp_m * 32 + mi * 16 + g;
        float* o0 = out + (size_t)r0 * N;
        float* o1 = out + (size_t)(r0 + 8) * N;
#pragma unroll
        for (int nj = 0; nj < 8; ++nj) {
            const int col = n0 + warp_n * 64 + nj * 8 + tg * 2;
            float2 v0 = make_float2(acc[mi][nj][0] + bcol0[nj], acc[mi][nj][1] + bcol1[nj]);
            float2 v1 = make_float2(acc[mi][nj][2] + bcol0[nj], acc[mi][nj][3] + bcol1[nj]);
            *reinterpret_cast<float2*>(o0 + col) = v0;
            *reinterpret_cast<float2*>(o1 + col) = v1;
        }
    }
}

// ---------------- launch ----------------
extern "C" void kernel_launch(void* const* d_in, const int* in_sizes, int n_in,
                              void* d_out, int out_size) {
    const float* x    = (const float*)d_in[0];
    const float* W    = (const float*)d_in[1];
    const float* bias = (const float*)d_in[2];
    float* out = (float*)d_out;

    prep_kernel<<<BIN_BLOCKS + WCONV_BLOCKS, 256>>>((const float4*)x, W);

    cudaFuncSetAttribute(gemm_kernel, cudaFuncAttributeMaxDynamicSharedMemorySize, DYN_SMEM);
    gemm_kernel<<<dim3(N / BN, M / BM), 256, DYN_SMEM>>>(out, bias);
}

// round 15
// speedup vs baseline: 1.1475x; 1.1475x over previous
#include <cuda_runtime.h>
#include <cuda_fp16.h>
#include <cstdint>
#include <cstddef>

// Problem sizes
static constexpr int M = 8192;   // tokens
static constexpr int K = 4096;   // in features
static constexpr int N = 4096;   // out features

// GEMM tiling: CTA 128x128x64, 4 warps (2 M x 2 N), warp tile 64x64, 128 threads.
// 3 stages x 32KB = 97KB -> 2 CTAs/SM: independent barriers hide skew; 64x64 warp
// tile keeps crossbar (1536 cyc/iter-pair) under the HMMA floor (2048 cyc).
static constexpr int BM = 128;
static constexpr int BN = 128;
static constexpr int BK = 64;                    // 64 fp16 = 128 B per row
static constexpr int NIT = K / BK;               // 64
static constexpr int STAGES = 3;
static constexpr int A_STAGE_BYTES = BM * 128;   // 16 KB
static constexpr int B_STAGE_BYTES = BN * 128;   // 16 KB
static constexpr int STAGE_BYTES = A_STAGE_BYTES + B_STAGE_BYTES;  // 32 KB
static constexpr int DYN_SMEM = 1024 + STAGES * STAGE_BYTES;       // ~97 KB

// Scratch (static device arrays are allowed; cudaMalloc is not)
__device__ __half g_A[(size_t)M * K];   // sign(x) as fp16, [M,K] row-major
__device__ __half g_B[(size_t)N * K];   // W^T as fp16,     [N,K] row-major

// ---------------- PTX helpers (baseline sm_103, no 'a' features) ----------------
__device__ __forceinline__ uint32_t smem_u32(const void* p) {
    uint32_t a;
    asm("{ .reg .u64 t; cvta.to.shared.u64 t, %1; cvt.u32.u64 %0, t; }" : "=r"(a) : "l"(p));
    return a;
}
__device__ __forceinline__ void cp_async16(uint32_t s, const void* g) {
    asm volatile("cp.async.cg.shared.global [%0], [%1], 16;" :: "r"(s), "l"(g));
}
__device__ __forceinline__ void cp_commit() {
    asm volatile("cp.async.commit_group;" ::: "memory");
}
template <int NWAIT>
__device__ __forceinline__ void cp_wait() {
    asm volatile("cp.async.wait_group %0;" :: "n"(NWAIT) : "memory");
}
__device__ __forceinline__ void ldsm_x4(uint32_t& r0, uint32_t& r1, uint32_t& r2, uint32_t& r3,
                                        uint32_t addr) {
    asm volatile("ldmatrix.sync.aligned.m8n8.x4.shared.b16 {%0,%1,%2,%3}, [%4];"
                 : "=r"(r0), "=r"(r1), "=r"(r2), "=r"(r3) : "r"(addr));
}
__device__ __forceinline__ void mma16816(float& d0, float& d1, float& d2, float& d3,
                                         uint32_t a0, uint32_t a1, uint32_t a2, uint32_t a3,
                                         uint32_t b0, uint32_t b1) {
    asm volatile(
        "mma.sync.aligned.m16n8k16.row.col.f32.f16.f16.f32 "
        "{%0,%1,%2,%3}, {%4,%5,%6,%7}, {%8,%9}, {%0,%1,%2,%3};"
        : "+f"(d0), "+f"(d1), "+f"(d2), "+f"(d3)
        : "r"(a0), "r"(a1), "r"(a2), "r"(a3), "r"(b0), "r"(b1));
}
// SW128-style swizzle: XOR 16B-chunk index with (row & 7)
__device__ __forceinline__ uint32_t swz(uint32_t off) { return off ^ ((off >> 3) & 0x70); }

// ---------------- Kernel 1: fused prep ----------------
static constexpr int BIN_BLOCKS = 4096;
static constexpr int WCONV_BLOCKS = (N / 32) * (K / 64);   // 8192
__global__ void prep_kernel(const float4* __restrict__ x4, const float* __restrict__ W) {
    if (blockIdx.x < BIN_BLOCKS) {
        const int n4 = (M * K) / 4;
        int i = blockIdx.x * 256 + threadIdx.x;
        const int stride = BIN_BLOCKS * 256;
        const __half one = __float2half_rn(1.0f);
        const __half neg = __float2half_rn(-1.0f);
        uint2* a8 = reinterpret_cast<uint2*>(g_A);
        for (; i < n4; i += stride) {
            float4 v = x4[i];
            __half2 h0 = __halves2half2(v.x > 0.0f ? one : neg, v.y > 0.0f ? one : neg);
            __half2 h1 = __halves2half2(v.z > 0.0f ? one : neg, v.w > 0.0f ? one : neg);
            uint2 pk;
            pk.x = *reinterpret_cast<uint32_t*>(&h0);
            pk.y = *reinterpret_cast<uint32_t*>(&h1);
            a8[i] = pk;
        }
    } else {
        __shared__ float t[64][33];
        const int bid = blockIdx.x - BIN_BLOCKS;
        const int n0 = (bid & 127) * 32;       // N/32 = 128
        const int k0 = (bid >> 7) * 64;
        const int tx = threadIdx.x & 31, ty = threadIdx.x >> 5;   // 32 x 8
#pragma unroll
        for (int r = 0; r < 8; ++r)
            t[ty + 8 * r][tx] = W[(size_t)(k0 + ty + 8 * r) * N + n0 + tx];
        __syncthreads();
#pragma unroll
        for (int r = 0; r < 4; ++r) {
            const int n = ty + 8 * r;          // 0..31
            const __half2 h = __floats2half2_rn(t[2 * tx][n], t[2 * tx + 1][n]);
            *reinterpret_cast<__half2*>(g_B + (size_t)(n0 + n) * K + k0 + 2 * tx) = h;
        }
    }
}

// ---------------- Kernel 2: mma.sync fp16 GEMM + bias ----------------
__device__ __forceinline__ void load_stage(uint32_t tile0, int m0, int n0, int k_it, int slot,
                                           int tid) {
    const int k0 = k_it * BK;
    const uint32_t sa = tile0 + slot * STAGE_BYTES;
    const uint32_t sbm = sa + A_STAGE_BYTES;
    // A: 1024 chunks; B: 1024 chunks; 2048 / 128 threads = 16 each
#pragma unroll
    for (int c = tid; c < 2048; c += 128) {
        const int r = (c & 1023) >> 3, j = c & 7;
        const uint32_t so = swz((uint32_t)(r * 128 + j * 16));
        if (c < 1024)
            cp_async16(sa + so, g_A + (((size_t)(m0 + r)) << 12) + k0 + (j << 3));
        else
            cp_async16(sbm + so, g_B + (((size_t)(n0 + r)) << 12) + k0 + (j << 3));
    }
}

// Load one kk-step's fragments for this warp: A 4x ldsm.x4, B 4x ldsm.x4.
__device__ __forceinline__ void load_frags(uint32_t af[4][4], uint32_t bf[8][2],
                                           uint32_t sa, uint32_t sbm,
                                           const uint32_t aoff[4], const uint32_t boff[4],
                                           uint32_t kx) {
#pragma unroll
    for (int mi = 0; mi < 4; ++mi)
        ldsm_x4(af[mi][0], af[mi][1], af[mi][2], af[mi][3], sa + (aoff[mi] ^ kx));
#pragma unroll
    for (int pj = 0; pj < 4; ++pj) {
        uint32_t r0, r1, r2, r3;
        ldsm_x4(r0, r1, r2, r3, sbm + (boff[pj] ^ kx));
        bf[pj * 2 + 0][0] = r0; bf[pj * 2 + 0][1] = r1;
        bf[pj * 2 + 1][0] = r2; bf[pj * 2 + 1][1] = r3;
    }
}

__global__ void __launch_bounds__(128, 2) gemm_kernel(float* __restrict__ out,
                                                      const float* __restrict__ bias) {
    extern __shared__ char smem[];
    const uint32_t tile0 = (smem_u32(smem) + 1023) & ~1023u;
    const int tid = threadIdx.x;
    const int wid = tid >> 5;
    const int lane = tid & 31;
    const int m0 = blockIdx.y * BM;
    const int n0 = blockIdx.x * BN;
    const int warp_m = wid & 1;        // 0..1 -> 64 rows each
    const int warp_n = wid >> 1;       // 0..1 -> 64 cols each

    // Swizzled ldmatrix offsets (kk=0).
    uint32_t aoff[4];
#pragma unroll
    for (int mi = 0; mi < 4; ++mi) {
        const int row = warp_m * 64 + mi * 16 + (lane & 15);
        aoff[mi] = swz((uint32_t)(row * 128) + (uint32_t)((lane >> 4) << 4));
    }
    uint32_t boff[4];
#pragma unroll
    for (int pj = 0; pj < 4; ++pj) {
        const int row = warp_n * 64 + pj * 16 + (lane & 7) + ((lane >> 4) << 3);
        boff[pj] = swz((uint32_t)(row * 128) + (uint32_t)(((lane >> 3) & 1) << 4));
    }

    float acc[4][8][4];   // [mi][nj][c]  (128 regs)
#pragma unroll
    for (int mi = 0; mi < 4; ++mi)
#pragma unroll
        for (int nj = 0; nj < 8; ++nj)
#pragma unroll
            for (int c = 0; c < 4; ++c) acc[mi][nj][c] = 0.0f;

    // Prologue: fill stages 0,1; both resident before the loop.
#pragma unroll
    for (int p = 0; p < STAGES - 1; ++p) {
        load_stage(tile0, m0, n0, p, p, tid);
        cp_commit();
    }
    cp_wait<0>();
    __syncthreads();

    // Full kk-step double buffer: A 2x16 regs, B 2x16 regs.
    uint32_t af[2][4][4];
    uint32_t bf[2][8][2];
    load_frags(af[0], bf[0], tile0, tile0 + A_STAGE_BYTES, aoff, boff, 0);

    for (int it = 0; it < NIT; ++it) {
        const uint32_t sa = tile0 + (it % STAGES) * STAGE_BYTES;
        const uint32_t sbm = sa + A_STAGE_BYTES;
        const uint32_t sa_n = tile0 + ((it + 1) % STAGES) * STAGE_BYTES;
        const uint32_t sbm_n = sa_n + A_STAGE_BYTES;
        const bool has_next = (it + 1 < NIT);

        // Issue loads for stage it+2 into slot (it+2)%3 (freed by barrier at end of it-1).
        if (it + STAGES - 1 < NIT)
            load_stage(tile0, m0, n0, it + STAGES - 1, (it + STAGES - 1) % STAGES, tid);
        cp_commit();

#pragma unroll
        for (int kk = 0; kk < 4; ++kk) {
            const int cur = kk & 1, nxt = cur ^ 1;
            // Prefetch kk+1 (same stage) or next iter's kk0 (stage it+1, resident since
            // wait<0> at end of iter it-1 / prologue).
            if (kk < 3)
                load_frags(af[nxt], bf[nxt], sa, sbm, aoff, boff, (uint32_t)((kk + 1) << 5));
            else if (has_next)
                load_frags(af[nxt], bf[nxt], sa_n, sbm_n, aoff, boff, 0);
            // 32 MMAs of latency cover for the prefetch above.
#pragma unroll
            for (int mi = 0; mi < 4; ++mi)
#pragma unroll
                for (int nj = 0; nj < 8; ++nj)
                    mma16816(acc[mi][nj][0], acc[mi][nj][1], acc[mi][nj][2], acc[mi][nj][3],
                             af[cur][mi][0], af[cur][mi][1], af[cur][mi][2], af[cur][mi][3],
                             bf[cur][nj][0], bf[cur][nj][1]);
        }

        // End-of-iter: all issued loads complete (stage it+2 resident for next iter's
        // kk3 prefetch); barrier frees slot it%3 for next iter's writers.
        cp_wait<0>();
        __syncthreads();
    }

    // Epilogue
    const int g = lane >> 2, tg = lane & 3;
    float bcol0[8], bcol1[8];
#pragma unroll
    for (int nj = 0; nj < 8; ++nj) {
        const int col = n0 + warp_n * 64 + nj * 8 + tg * 2;
        bcol0[nj] = __ldg(bias + col);
        bcol1[nj] = __ldg(bias + col + 1);
    }
#pragma unroll
    for (int mi = 0; mi < 4; ++mi) {
        const int r0 = m0 + warp_m * 64 + mi * 16 + g;
        float* o0 = out + (size_t)r0 * N;
        float* o1 = out + (size_t)(r0 + 8) * N;
#pragma unroll
        for (int nj = 0; nj < 8; ++nj) {
            const int col = n0 + warp_n * 64 + nj * 8 + tg * 2;
            float2 v0 = make_float2(acc[mi][nj][0] + bcol0[nj], acc[mi][nj][1] + bcol1[nj]);
            float2 v1 = make_float2(acc[mi][nj][2] + bcol0[nj], acc[mi][nj][3] + bcol1[nj]);
            *reinterpret_cast<float2*>(o0 + col) = v0;
            *reinterpret_cast<float2*>(o1 + col) = v1;
        }
    }
}

// ---------------- launch ----------------
extern "C" void kernel_launch(void* const* d_in, const int* in_sizes, int n_in,
                              void* d_out, int out_size) {
    const float* x    = (const float*)d_in[0];
    const float* W    = (const float*)d_in[1];
    const float* bias = (const float*)d_in[2];
    float* out = (float*)d_out;

    prep_kernel<<<BIN_BLOCKS + WCONV_BLOCKS, 256>>>((const float4*)x, W);

    cudaFuncSetAttribute(gemm_kernel, cudaFuncAttributeMaxDynamicSharedMemorySize, DYN_SMEM);
    gemm_kernel<<<dim3(N / BN, M / BM), 128, DYN_SMEM>>>(out, bias);
}

// round 16
// speedup vs baseline: 1.2157x; 1.0594x over previous
#include <cuda_runtime.h>
#include <cuda_fp16.h>
#include <cstdint>
#include <cstddef>

// Problem sizes
static constexpr int M = 8192;   // tokens
static constexpr int K = 4096;   // in features
static constexpr int N = 4096;   // out features

// GEMM tiling: CTA 128x256x64, 8 warps (2 M x 4 N), warp tile 64x64, 256 threads.
// Barrier once per TWO k-iterations (4 stages, pair-wise pipeline).
static constexpr int BM = 128;
static constexpr int BN = 256;
static constexpr int BK = 64;                    // 64 fp16 = 128 B per row
static constexpr int NIT = K / BK;               // 64
static constexpr int STAGES = 4;
static constexpr int A_STAGE_BYTES = BM * 128;   // 16 KB
static constexpr int B_STAGE_BYTES = BN * 128;   // 32 KB
static constexpr int STAGE_BYTES = A_STAGE_BYTES + B_STAGE_BYTES;  // 48 KB
static constexpr int DYN_SMEM = 1024 + STAGES * STAGE_BYTES;       // ~193 KB

// Scratch (static device arrays are allowed; cudaMalloc is not)
__device__ __half g_A[(size_t)M * K];   // sign(x) as fp16, [M,K] row-major
__device__ __half g_B[(size_t)N * K];   // W^T as fp16,     [N,K] row-major

// ---------------- PTX helpers (baseline sm_103, no 'a' features) ----------------
__device__ __forceinline__ uint32_t smem_u32(const void* p) {
    uint32_t a;
    asm("{ .reg .u64 t; cvta.to.shared.u64 t, %1; cvt.u32.u64 %0, t; }" : "=r"(a) : "l"(p));
    return a;
}
__device__ __forceinline__ void cp_async16(uint32_t s, const void* g) {
    asm volatile("cp.async.cg.shared.global [%0], [%1], 16;" :: "r"(s), "l"(g));
}
__device__ __forceinline__ void cp_commit() {
    asm volatile("cp.async.commit_group;" ::: "memory");
}
template <int NWAIT>
__device__ __forceinline__ void cp_wait() {
    asm volatile("cp.async.wait_group %0;" :: "n"(NWAIT) : "memory");
}
__device__ __forceinline__ void ldsm_x4(uint32_t& r0, uint32_t& r1, uint32_t& r2, uint32_t& r3,
                                        uint32_t addr) {
    asm volatile("ldmatrix.sync.aligned.m8n8.x4.shared.b16 {%0,%1,%2,%3}, [%4];"
                 : "=r"(r0), "=r"(r1), "=r"(r2), "=r"(r3) : "r"(addr));
}
__device__ __forceinline__ void mma16816(float& d0, float& d1, float& d2, float& d3,
                                         uint32_t a0, uint32_t a1, uint32_t a2, uint32_t a3,
                                         uint32_t b0, uint32_t b1) {
    asm volatile(
        "mma.sync.aligned.m16n8k16.row.col.f32.f16.f16.f32 "
        "{%0,%1,%2,%3}, {%4,%5,%6,%7}, {%8,%9}, {%0,%1,%2,%3};"
        : "+f"(d0), "+f"(d1), "+f"(d2), "+f"(d3)
        : "r"(a0), "r"(a1), "r"(a2), "r"(a3), "r"(b0), "r"(b1));
}
// SW128-style swizzle: XOR 16B-chunk index with (row & 7)
__device__ __forceinline__ uint32_t swz(uint32_t off) { return off ^ ((off >> 3) & 0x70); }

// ---------------- Kernel 1: fused prep ----------------
static constexpr int BIN_BLOCKS = 4096;
static constexpr int WCONV_BLOCKS = (N / 32) * (K / 64);   // 8192
__global__ void prep_kernel(const float4* __restrict__ x4, const float* __restrict__ W) {
    if (blockIdx.x < BIN_BLOCKS) {
        const int n4 = (M * K) / 4;
        int i = blockIdx.x * 256 + threadIdx.x;
        const int stride = BIN_BLOCKS * 256;
        const __half one = __float2half_rn(1.0f);
        const __half neg = __float2half_rn(-1.0f);
        uint2* a8 = reinterpret_cast<uint2*>(g_A);
        for (; i < n4; i += stride) {
            float4 v = x4[i];
            __half2 h0 = __halves2half2(v.x > 0.0f ? one : neg, v.y > 0.0f ? one : neg);
            __half2 h1 = __halves2half2(v.z > 0.0f ? one : neg, v.w > 0.0f ? one : neg);
            uint2 pk;
            pk.x = *reinterpret_cast<uint32_t*>(&h0);
            pk.y = *reinterpret_cast<uint32_t*>(&h1);
            a8[i] = pk;
        }
    } else {
        __shared__ float t[64][33];
        const int bid = blockIdx.x - BIN_BLOCKS;
        const int n0 = (bid & 127) * 32;       // N/32 = 128
        const int k0 = (bid >> 7) * 64;
        const int tx = threadIdx.x & 31, ty = threadIdx.x >> 5;   // 32 x 8
#pragma unroll
        for (int r = 0; r < 8; ++r)
            t[ty + 8 * r][tx] = W[(size_t)(k0 + ty + 8 * r) * N + n0 + tx];
        __syncthreads();
#pragma unroll
        for (int r = 0; r < 4; ++r) {
            const int n = ty + 8 * r;          // 0..31
            const __half2 h = __floats2half2_rn(t[2 * tx][n], t[2 * tx + 1][n]);
            *reinterpret_cast<__half2*>(g_B + (size_t)(n0 + n) * K + k0 + 2 * tx) = h;
        }
    }
}

// ---------------- Kernel 2: mma.sync fp16 GEMM + bias ----------------
__device__ __forceinline__ void load_stage(uint32_t tile0, int m0, int n0, int k_it, int slot,
                                           int tid) {
    const int k0 = k_it * BK;
    const uint32_t sa = tile0 + slot * STAGE_BYTES;
    const uint32_t sbm = sa + A_STAGE_BYTES;
    // A: 1024 chunks; B: 2048 chunks; 3072 / 256 thr = 12 each
#pragma unroll
    for (int c = tid; c < 3072; c += 256) {
        if (c < 1024) {
            const int r = c >> 3, j = c & 7;
            cp_async16(sa + swz((uint32_t)(r * 128 + j * 16)),
                       g_A + (((size_t)(m0 + r)) << 12) + k0 + (j << 3));
        } else {
            const int c2 = c - 1024;
            const int r = c2 >> 3, j = c2 & 7;
            cp_async16(sbm + swz((uint32_t)(r * 128 + j * 16)),
                       g_B + (((size_t)(n0 + r)) << 12) + k0 + (j << 3));
        }
    }
}

// Load one kk-step's fragments for this warp: A 4x ldsm.x4, B 4x ldsm.x4.
__device__ __forceinline__ void load_frags(uint32_t af[4][4], uint32_t bf[8][2],
                                           uint32_t sa, uint32_t sbm,
                                           const uint32_t aoff[4], const uint32_t boff[4],
                                           uint32_t kx) {
#pragma unroll
    for (int mi = 0; mi < 4; ++mi)
        ldsm_x4(af[mi][0], af[mi][1], af[mi][2], af[mi][3], sa + (aoff[mi] ^ kx));
#pragma unroll
    for (int pj = 0; pj < 4; ++pj) {
        uint32_t r0, r1, r2, r3;
        ldsm_x4(r0, r1, r2, r3, sbm + (boff[pj] ^ kx));
        bf[pj * 2 + 0][0] = r0; bf[pj * 2 + 0][1] = r1;
        bf[pj * 2 + 1][0] = r2; bf[pj * 2 + 1][1] = r3;
    }
}

__global__ void __launch_bounds__(256, 1) gemm_kernel(float* __restrict__ out,
                                                      const float* __restrict__ bias) {
    extern __shared__ char smem[];
    const uint32_t tile0 = (smem_u32(smem) + 1023) & ~1023u;
    const int tid = threadIdx.x;
    const int wid = tid >> 5;
    const int lane = tid & 31;
    const int m0 = blockIdx.y * BM;
    const int n0 = blockIdx.x * BN;
    const int warp_m = wid & 1;        // 0..1 -> 64 rows each
    const int warp_n = wid >> 1;       // 0..3 -> 64 cols each

    // Swizzled ldmatrix offsets (kk=0).
    uint32_t aoff[4];
#pragma unroll
    for (int mi = 0; mi < 4; ++mi) {
        const int row = warp_m * 64 + mi * 16 + (lane & 15);
        aoff[mi] = swz((uint32_t)(row * 128) + (uint32_t)((lane >> 4) << 4));
    }
    uint32_t boff[4];
#pragma unroll
    for (int pj = 0; pj < 4; ++pj) {
        const int row = warp_n * 64 + pj * 16 + (lane & 7) + ((lane >> 4) << 3);
        boff[pj] = swz((uint32_t)(row * 128) + (uint32_t)(((lane >> 3) & 1) << 4));
    }

    float acc[4][8][4];   // [mi][nj][c]  (128 regs)
#pragma unroll
    for (int mi = 0; mi < 4; ++mi)
#pragma unroll
        for (int nj = 0; nj < 8; ++nj)
#pragma unroll
            for (int c = 0; c < 4; ++c) acc[mi][nj][c] = 0.0f;

    // Prologue: stages 0,1 resident before the first pair.
    load_stage(tile0, m0, n0, 0, 0, tid);
    load_stage(tile0, m0, n0, 1, 1, tid);
    cp_commit();
    cp_wait<0>();
    __syncthreads();

    // Full kk-step double buffer: A 2x16 regs, B 2x16 regs.
    uint32_t af[2][4][4];
    uint32_t bf[2][8][2];
    load_frags(af[0], bf[0], tile0, tile0 + A_STAGE_BYTES, aoff, boff, 0);

    // Pair loop: ONE wait+barrier per two k-iterations.
    for (int p = 0; p < NIT / 2; ++p) {
        const int it0 = 2 * p;
        const uint32_t sa0 = tile0 + (it0 % STAGES) * STAGE_BYTES;
        const uint32_t sbm0 = sa0 + A_STAGE_BYTES;
        const uint32_t sa1 = tile0 + ((it0 + 1) % STAGES) * STAGE_BYTES;
        const uint32_t sbm1 = sa1 + A_STAGE_BYTES;
        const uint32_t sa2 = tile0 + ((it0 + 2) % STAGES) * STAGE_BYTES;
        const uint32_t sbm2 = sa2 + A_STAGE_BYTES;
        const bool has_next_pair = (it0 + 2 < NIT);

        // Issue loads for stages it0+2 and it0+3 (slots freed by the previous pair's
        // barrier: pair p-1 last read those slots before its mid-pair barrier).
        if (it0 + 2 < NIT)
            load_stage(tile0, m0, n0, it0 + 2, (it0 + 2) % STAGES, tid);
        if (it0 + 3 < NIT)
            load_stage(tile0, m0, n0, it0 + 3, (it0 + 3) % STAGES, tid);
        cp_commit();

        // ---- iteration it0: kk = 0..3 ----
#pragma unroll
        for (int kk = 0; kk < 4; ++kk) {
            const int cur = kk & 1, nxt = cur ^ 1;
            if (kk < 3)
                load_frags(af[nxt], bf[nxt], sa0, sbm0, aoff, boff, (uint32_t)((kk + 1) << 5));
            else
                load_frags(af[nxt], bf[nxt], sa1, sbm1, aoff, boff, 0);   // it1 kk0
#pragma unroll
            for (int mi = 0; mi < 4; ++mi)
#pragma unroll
                for (int nj = 0; nj < 8; ++nj)
                    mma16816(acc[mi][nj][0], acc[mi][nj][1], acc[mi][nj][2], acc[mi][nj][3],
                             af[cur][mi][0], af[cur][mi][1], af[cur][mi][2], af[cur][mi][3],
                             bf[cur][nj][0], bf[cur][nj][1]);
        }

        // ---- iteration it0+1: kk = 0..2 ----
#pragma unroll
        for (int kk = 0; kk < 3; ++kk) {
            const int cur = kk & 1, nxt = cur ^ 1;
            load_frags(af[nxt], bf[nxt], sa1, sbm1, aoff, boff, (uint32_t)((kk + 1) << 5));
#pragma unroll
            for (int mi = 0; mi < 4; ++mi)
#pragma unroll
                for (int nj = 0; nj < 8; ++nj)
                    mma16816(acc[mi][nj][0], acc[mi][nj][1], acc[mi][nj][2], acc[mi][nj][3],
                             af[cur][mi][0], af[cur][mi][1], af[cur][mi][2], af[cur][mi][3],
                             bf[cur][nj][0], bf[cur][nj][1]);
        }

        // Mid-pair sync: stages it0+2, it0+3 now resident; all reads of the slots
        // the NEXT pair will overwrite have completed above.
        cp_wait<0>();
        __syncthreads();

        // ---- iteration it0+1: kk = 3 (buffer 1), prefetching next pair's kk0 ----
        if (has_next_pair)
            load_frags(af[0], bf[0], sa2, sbm2, aoff, boff, 0);
#pragma unroll
        for (int mi = 0; mi < 4; ++mi)
#pragma unroll
            for (int nj = 0; nj < 8; ++nj)
                mma16816(acc[mi][nj][0], acc[mi][nj][1], acc[mi][nj][2], acc[mi][nj][3],
                         af[1][mi][0], af[1][mi][1], af[1][mi][2], af[1][mi][3],
                         bf[1][nj][0], bf[1][nj][1]);
    }

    // Epilogue
    const int g = lane >> 2, tg = lane & 3;
    float bcol0[8], bcol1[8];
#pragma unroll
    for (int nj = 0; nj < 8; ++nj) {
        const int col = n0 + warp_n * 64 + nj * 8 + tg * 2;
        bcol0[nj] = __ldg(bias + col);
        bcol1[nj] = __ldg(bias + col + 1);
    }
#pragma unroll
    for (int mi = 0; mi < 4; ++mi) {
        const int r0 = m0 + warp_m * 64 + mi * 16 + g;
        float* o0 = out + (size_t)r0 * N;
        float* o1 = out + (size_t)(r0 + 8) * N;
#pragma unroll
        for (int nj = 0; nj < 8; ++nj) {
            const int col = n0 + warp_n * 64 + nj * 8 + tg * 2;
            float2 v0 = make_float2(acc[mi][nj][0] + bcol0[nj], acc[mi][nj][1] + bcol1[nj]);
            float2 v1 = make_float2(acc[mi][nj][2] + bcol0[nj], acc[mi][nj][3] + bcol1[nj]);
            *reinterpret_cast<float2*>(o0 + col) = v0;
            *reinterpret_cast<float2*>(o1 + col) = v1;
        }
    }
}

// ---------------- launch ----------------
extern "C" void kernel_launch(void* const* d_in, const int* in_sizes, int n_in,
                              void* d_out, int out_size) {
    const float* x    = (const float*)d_in[0];
    const float* W    = (const float*)d_in[1];
    const float* bias = (const float*)d_in[2];
    float* out = (float*)d_out;

    prep_kernel<<<BIN_BLOCKS + WCONV_BLOCKS, 256>>>((const float4*)x, W);

    cudaFuncSetAttribute(gemm_kernel, cudaFuncAttributeMaxDynamicSharedMemorySize, DYN_SMEM);
    gemm_kernel<<<dim3(N / BN, M / BM), 256, DYN_SMEM>>>(out, bias);
}

// round 17
// speedup vs baseline: 1.2189x; 1.0026x over previous
#include <cuda_runtime.h>
#include <cuda_fp16.h>
#include <cstdint>
#include <cstddef>

// Problem sizes
static constexpr int M = 8192;   // tokens
static constexpr int K = 4096;   // in features
static constexpr int N = 4096;   // out features

// GEMM tiling: CTA 128x256x64, 8 warps (2 M x 4 N), warp tile 64x64, 256 threads.
// Per-stage mbarrier producer/consumer pipeline: no CTA-wide __syncthreads in the
// main loop; warp skew absorbed instead of convoyed.
static constexpr int BM = 128;
static constexpr int BN = 256;
static constexpr int BK = 64;                    // 64 fp16 = 128 B per row
static constexpr int NIT = K / BK;               // 64
static constexpr int STAGES = 4;
static constexpr int A_STAGE_BYTES = BM * 128;   // 16 KB
static constexpr int B_STAGE_BYTES = BN * 128;   // 32 KB
static constexpr int STAGE_BYTES = A_STAGE_BYTES + B_STAGE_BYTES;  // 48 KB
static constexpr int DYN_SMEM = 1024 + STAGES * STAGE_BYTES;       // ~193 KB

// Scratch (static device arrays are allowed; cudaMalloc is not)
__device__ __half g_A[(size_t)M * K];   // sign(x) as fp16, [M,K] row-major
__device__ __half g_B[(size_t)N * K];   // W^T as fp16,     [N,K] row-major

// ---------------- PTX helpers (baseline sm_103, no 'a' features) ----------------
__device__ __forceinline__ uint32_t smem_u32(const void* p) {
    uint32_t a;
    asm("{ .reg .u64 t; cvta.to.shared.u64 t, %1; cvt.u32.u64 %0, t; }" : "=r"(a) : "l"(p));
    return a;
}
__device__ __forceinline__ void cp_async16(uint32_t s, const void* g) {
    asm volatile("cp.async.cg.shared.global [%0], [%1], 16;" :: "r"(s), "l"(g));
}
__device__ __forceinline__ void mbar_init(uint32_t a, uint32_t cnt) {
    asm volatile("mbarrier.init.shared.b64 [%0], %1;" :: "r"(a), "r"(cnt) : "memory");
}
__device__ __forceinline__ void mbar_arrive(uint32_t a) {
    asm volatile("mbarrier.arrive.shared.b64 _, [%0];" :: "r"(a) : "memory");
}
__device__ __forceinline__ void cp_async_mbar_arrive(uint32_t a) {
    asm volatile("cp.async.mbarrier.arrive.noinc.shared.b64 [%0];" :: "r"(a) : "memory");
}
__device__ __forceinline__ void mbar_wait(uint32_t a, uint32_t parity) {
    asm volatile(
        "{\n\t"
        ".reg .pred P1;\n\t"
        "LAB_WAIT_%=:\n\t"
        "mbarrier.try_wait.parity.acquire.cta.shared::cta.b64 P1, [%0], %1, 0x989680;\n\t"
        "@P1 bra LAB_DONE_%=;\n\t"
        "bra LAB_WAIT_%=;\n\t"
        "LAB_DONE_%=:\n\t"
        "}"
        :: "r"(a), "r"(parity) : "memory");
}
__device__ __forceinline__ void ldsm_x4(uint32_t& r0, uint32_t& r1, uint32_t& r2, uint32_t& r3,
                                        uint32_t addr) {
    asm volatile("ldmatrix.sync.aligned.m8n8.x4.shared.b16 {%0,%1,%2,%3}, [%4];"
                 : "=r"(r0), "=r"(r1), "=r"(r2), "=r"(r3) : "r"(addr));
}
__device__ __forceinline__ void mma16816(float& d0, float& d1, float& d2, float& d3,
                                         uint32_t a0, uint32_t a1, uint32_t a2, uint32_t a3,
                                         uint32_t b0, uint32_t b1) {
    asm volatile(
        "mma.sync.aligned.m16n8k16.row.col.f32.f16.f16.f32 "
        "{%0,%1,%2,%3}, {%4,%5,%6,%7}, {%8,%9}, {%0,%1,%2,%3};"
        : "+f"(d0), "+f"(d1), "+f"(d2), "+f"(d3)
        : "r"(a0), "r"(a1), "r"(a2), "r"(a3), "r"(b0), "r"(b1));
}
// SW128-style swizzle: XOR 16B-chunk index with (row & 7)
__device__ __forceinline__ uint32_t swz(uint32_t off) { return off ^ ((off >> 3) & 0x70); }

// ---------------- Kernel 1: fused prep ----------------
static constexpr int BIN_BLOCKS = 4096;
static constexpr int WCONV_BLOCKS = (N / 32) * (K / 64);   // 8192
__global__ void prep_kernel(const float4* __restrict__ x4, const float* __restrict__ W) {
    if (blockIdx.x < BIN_BLOCKS) {
        const int n4 = (M * K) / 4;
        int i = blockIdx.x * 256 + threadIdx.x;
        const int stride = BIN_BLOCKS * 256;
        const __half one = __float2half_rn(1.0f);
        const __half neg = __float2half_rn(-1.0f);
        uint2* a8 = reinterpret_cast<uint2*>(g_A);
        for (; i < n4; i += stride) {
            float4 v = x4[i];
            __half2 h0 = __halves2half2(v.x > 0.0f ? one : neg, v.y > 0.0f ? one : neg);
            __half2 h1 = __halves2half2(v.z > 0.0f ? one : neg, v.w > 0.0f ? one : neg);
            uint2 pk;
            pk.x = *reinterpret_cast<uint32_t*>(&h0);
            pk.y = *reinterpret_cast<uint32_t*>(&h1);
            a8[i] = pk;
        }
    } else {
        __shared__ float t[64][33];
        const int bid = blockIdx.x - BIN_BLOCKS;
        const int n0 = (bid & 127) * 32;       // N/32 = 128
        const int k0 = (bid >> 7) * 64;
        const int tx = threadIdx.x & 31, ty = threadIdx.x >> 5;   // 32 x 8
#pragma unroll
        for (int r = 0; r < 8; ++r)
            t[ty + 8 * r][tx] = W[(size_t)(k0 + ty + 8 * r) * N + n0 + tx];
        __syncthreads();
#pragma unroll
        for (int r = 0; r < 4; ++r) {
            const int n = ty + 8 * r;          // 0..31
            const __half2 h = __floats2half2_rn(t[2 * tx][n], t[2 * tx + 1][n]);
            *reinterpret_cast<__half2*>(g_B + (size_t)(n0 + n) * K + k0 + 2 * tx) = h;
        }
    }
}

// ---------------- Kernel 2: mma.sync fp16 GEMM + bias ----------------
__device__ __forceinline__ void load_stage(uint32_t tile0, int m0, int n0, int k_it, int slot,
                                           int tid) {
    const int k0 = k_it * BK;
    const uint32_t sa = tile0 + slot * STAGE_BYTES;
    const uint32_t sbm = sa + A_STAGE_BYTES;
    // A: 1024 chunks; B: 2048 chunks; 3072 / 256 thr = 12 each
#pragma unroll
    for (int c = tid; c < 3072; c += 256) {
        if (c < 1024) {
            const int r = c >> 3, j = c & 7;
            cp_async16(sa + swz((uint32_t)(r * 128 + j * 16)),
                       g_A + (((size_t)(m0 + r)) << 12) + k0 + (j << 3));
        } else {
            const int c2 = c - 1024;
            const int r = c2 >> 3, j = c2 & 7;
            cp_async16(sbm + swz((uint32_t)(r * 128 + j * 16)),
                       g_B + (((size_t)(n0 + r)) << 12) + k0 + (j << 3));
        }
    }
}

// Load one kk-step's fragments for this warp: A 4x ldsm.x4, B 4x ldsm.x4.
__device__ __forceinline__ void load_frags(uint32_t af[4][4], uint32_t bf[8][2],
                                           uint32_t sa, uint32_t sbm,
                                           const uint32_t aoff[4], const uint32_t boff[4],
                                           uint32_t kx) {
#pragma unroll
    for (int mi = 0; mi < 4; ++mi)
        ldsm_x4(af[mi][0], af[mi][1], af[mi][2], af[mi][3], sa + (aoff[mi] ^ kx));
#pragma unroll
    for (int pj = 0; pj < 4; ++pj) {
        uint32_t r0, r1, r2, r3;
        ldsm_x4(r0, r1, r2, r3, sbm + (boff[pj] ^ kx));
        bf[pj * 2 + 0][0] = r0; bf[pj * 2 + 0][1] = r1;
        bf[pj * 2 + 1][0] = r2; bf[pj * 2 + 1][1] = r3;
    }
}

__global__ void __launch_bounds__(256, 1) gemm_kernel(float* __restrict__ out,
                                                      const float* __restrict__ bias) {
    extern __shared__ char smem[];
    const uint32_t sb = smem_u32(smem);
    const uint32_t tile0 = (sb + 64 + 1023) & ~1023u;
    const int tid = threadIdx.x;
    const int wid = tid >> 5;
    const int lane = tid & 31;
    const int m0 = blockIdx.y * BM;
    const int n0 = blockIdx.x * BN;
    const int warp_m = wid & 1;        // 0..1 -> 64 rows each
    const int warp_n = wid >> 1;       // 0..3 -> 64 cols each

    // mbarriers: full[s] = sb + 8s (256 arrivals via cp.async); empty[s] = sb + 32 + 8s (8 warps).
    if (tid == 0) {
#pragma unroll
        for (int s = 0; s < STAGES; ++s) {
            mbar_init(sb + 8 * s, 256);
            mbar_init(sb + 32 + 8 * s, 8);
        }
    }
    __syncthreads();

    // Swizzled ldmatrix offsets (kk=0).
    uint32_t aoff[4];
#pragma unroll
    for (int mi = 0; mi < 4; ++mi) {
        const int row = warp_m * 64 + mi * 16 + (lane & 15);
        aoff[mi] = swz((uint32_t)(row * 128) + (uint32_t)((lane >> 4) << 4));
    }
    uint32_t boff[4];
#pragma unroll
    for (int pj = 0; pj < 4; ++pj) {
        const int row = warp_n * 64 + pj * 16 + (lane & 7) + ((lane >> 4) << 3);
        boff[pj] = swz((uint32_t)(row * 128) + (uint32_t)(((lane >> 3) & 1) << 4));
    }

    float acc[4][8][4];   // [mi][nj][c]  (128 regs)
#pragma unroll
    for (int mi = 0; mi < 4; ++mi)
#pragma unroll
        for (int nj = 0; nj < 8; ++nj)
#pragma unroll
            for (int c = 0; c < 4; ++c) acc[mi][nj][c] = 0.0f;

    // Prologue: load stages 0..2, each arriving on its full barrier as copies land.
#pragma unroll
    for (int p = 0; p < STAGES - 1; ++p) {
        load_stage(tile0, m0, n0, p, p, tid);
        cp_async_mbar_arrive(sb + 8 * p);
    }

    // Wait stage 0 full (phase 0), preload kk0 fragments.
    mbar_wait(sb + 0, 0);
    uint32_t af[2][4][4];
    uint32_t bf[2][8][2];
    load_frags(af[0], bf[0], tile0, tile0 + A_STAGE_BYTES, aoff, boff, 0);

    for (int it = 0; it < NIT; ++it) {
        const int s = it & 3;
        const uint32_t sa = tile0 + s * STAGE_BYTES;
        const uint32_t sbm = sa + A_STAGE_BYTES;
        const uint32_t sa_n = tile0 + ((it + 1) & 3) * STAGE_BYTES;
        const uint32_t sbm_n = sa_n + A_STAGE_BYTES;
        const bool has_next = (it + 1 < NIT);

        // Producer: load stage it+3 into slot (it+3)&3 once all warps released it.
        const int ld = it + 3;
        if (ld < NIT) {
            const int slot = ld & 3;
            const uint32_t wr = (uint32_t)(ld >> 2);
            mbar_wait(sb + 32 + 8 * slot, (wr + 1) & 1);   // empty[slot]
            load_stage(tile0, m0, n0, ld, slot, tid);
            cp_async_mbar_arrive(sb + 8 * slot);           // full[slot]
        }

#pragma unroll
        for (int kk = 0; kk < 4; ++kk) {
            const int cur = kk & 1, nxt = cur ^ 1;
            if (kk < 3) {
                load_frags(af[nxt], bf[nxt], sa, sbm, aoff, boff, (uint32_t)((kk + 1) << 5));
            } else if (has_next) {
                // Consumer wait: stage it+1 full (round (it+1)/4, parity of that round).
                mbar_wait(sb + 8 * ((it + 1) & 3), (uint32_t)(((it + 1) >> 2) & 1));
                load_frags(af[nxt], bf[nxt], sa_n, sbm_n, aoff, boff, 0);
            }
            if (kk == 2) {
                // Last read of stage `s` just completed (kk3 fragments are in regs).
                if (lane == 0) mbar_arrive(sb + 32 + 8 * s);   // empty[s]
            }
#pragma unroll
            for (int mi = 0; mi < 4; ++mi)
#pragma unroll
                for (int nj = 0; nj < 8; ++nj)
                    mma16816(acc[mi][nj][0], acc[mi][nj][1], acc[mi][nj][2], acc[mi][nj][3],
                             af[cur][mi][0], af[cur][mi][1], af[cur][mi][2], af[cur][mi][3],
                             bf[cur][nj][0], bf[cur][nj][1]);
        }
    }

    // Epilogue
    const int g = lane >> 2, tg = lane & 3;
    float bcol0[8], bcol1[8];
#pragma unroll
    for (int nj = 0; nj < 8; ++nj) {
        const int col = n0 + warp_n * 64 + nj * 8 + tg * 2;
        bcol0[nj] = __ldg(bias + col);
        bcol1[nj] = __ldg(bias + col + 1);
    }
#pragma unroll
    for (int mi = 0; mi < 4; ++mi) {
        const int r0 = m0 + warp_m * 64 + mi * 16 + g;
        float* o0 = out + (size_t)r0 * N;
        float* o1 = out + (size_t)(r0 + 8) * N;
#pragma unroll
        for (int nj = 0; nj < 8; ++nj) {
            const int col = n0 + warp_n * 64 + nj * 8 + tg * 2;
            float2 v0 = make_float2(acc[mi][nj][0] + bcol0[nj], acc[mi][nj][1] + bcol1[nj]);
            float2 v1 = make_float2(acc[mi][nj][2] + bcol0[nj], acc[mi][nj][3] + bcol1[nj]);
            *reinterpret_cast<float2*>(o0 + col) = v0;
            *reinterpret_cast<float2*>(o1 + col) = v1;
        }
    }
}

// ---------------- launch ----------------
extern "C" void kernel_launch(void* const* d_in, const int* in_sizes, int n_in,
                              void* d_out, int out_size) {
    const float* x    = (const float*)d_in[0];
    const float* W    = (const float*)d_in[1];
    const float* bias = (const float*)d_in[2];
    float* out = (float*)d_out;

    prep_kernel<<<BIN_BLOCKS + WCONV_BLOCKS, 256>>>((const float4*)x, W);

    cudaFuncSetAttribute(gemm_kernel, cudaFuncAttributeMaxDynamicSharedMemorySize, DYN_SMEM);
    gemm_kernel<<<dim3(N / BN, M / BM), 256, DYN_SMEM>>>(out, bias);
}